// round 12
// baseline (speedup 1.0000x reference)
#include <cuda_runtime.h>
#include <cuda_fp16.h>
#include <math.h>

// ---------------- problem constants ----------------
#define NB    8      // batch
#define BCAP  32     // B_ input capsules
#define NC    32     // C_ output capsules
#define WIN   14
#define WOUT  6
#define WW    36     // WOUT*WOUT
#define BKK   288    // K*K*B_
#define CWW   1152   // C_*WOUT*WOUT
#define EPSV  1e-10f
#define HALF_LN2PI 0.91893853320467274178f
#define LOG2E 1.4426950408889634074f
#define FULLM 0xffffffffu

// ---------------- device scratch (static: allocation-free) ----------------
__device__ __half g_votes_h[(size_t)NB * CWW * BKK * 16];  // 81 MB fp16 votes [b][x][i][h]
__device__ float  g_ap[(size_t)NB * CWW * BKK];            // R numerators [b][x][i]
__device__ float  g_part[NB * 36 * BKK];                   // stage-1 partial sums
__device__ float  g_denom[NB * BKK];                       // denom[b][i]

__device__ __forceinline__ float4 rowmul(float4 wr, float4 p0, float4 p1, float4 p2, float4 p3) {
    float4 r;
    r.x = wr.x*p0.x + wr.y*p1.x + wr.z*p2.x + wr.w*p3.x;
    r.y = wr.x*p0.y + wr.y*p1.y + wr.z*p2.y + wr.w*p3.y;
    r.z = wr.x*p0.z + wr.y*p1.z + wr.z*p2.z + wr.w*p3.z;
    r.w = wr.x*p0.w + wr.y*p1.w + wr.z*p2.w + wr.w*p3.w;
    return r;
}

__device__ __forceinline__ unsigned int h2u(__half2 x) {
    return *reinterpret_cast<unsigned int*>(&x);
}

__device__ __forceinline__ float ex2f(float x) {
    float y;
    asm("ex2.approx.ftz.f32 %0, %1;" : "=f"(y) : "f"(x));
    return y;
}

__device__ __forceinline__ float rcpf(float x) {
    float y;
    asm("rcp.approx.ftz.f32 %0, %1;" : "=f"(y) : "f"(x));
    return y;
}

// One block per output column. blockIdx.x = x = s*32 + c. 288 threads, 9 warps.
// Stats mapping is WARP-LOCAL: warp w owns capsules i in [32w, 32w+32).
// Thread (lane) takes sub = lane&3, q = lane>>2 and reduces i = 32w+sub+4k,
// k=0..7, h-pair q. Rw is exchanged via __shfl (thread t computed R for i=t,
// which lives in the same warp) -> NO block-wide barrier before stats in
// phases 1/2; each warp proceeds as soon as its own vote loads land.
// p-pass: thread t re-reads its OWN row V[i=t][0..15] (32B, L1/L2-hot), sums
// over h serially; g_ap store is one coalesced 1152B line per block.
// PHASE 0: compute+store fp16 votes (barrier for the gmem round-trip, row kept
// in regs). 1: mid iter (2 barriers). 2: outputs (1 barrier).
template <int PHASE>
__global__ __launch_bounds__(BKK, 5)
void em_kernel(const float* __restrict__ poses, const float* __restrict__ act,
               const float* __restrict__ Wt, const float* __restrict__ beta_v,
               const float* __restrict__ beta_a, const float* __restrict__ lam,
               float* __restrict__ out)
{
    const int x   = blockIdx.x;
    const int b   = blockIdx.y;
    const int c   = x & 31;
    const int s   = x >> 5;
    const int yw  = s / WOUT;
    const int xw  = s - yw * WOUT;
    const int t   = threadIdx.x;
    const int w   = t >> 5;        // warp 0..8
    const int lane = t & 31;
    const int sub = lane & 3;      // i-subgroup within warp
    const int q   = lane >> 2;     // 0..7 (h-pair)
    const size_t colbase = (size_t)(b * CWW + x) * BKK;

    __shared__ float2 redm[9][8];        // Rw*V partials (float[9][16] view)
    __shared__ float2 redv[9][8];        // Rw*V^2 partials
    __shared__ float  red2[9];           // Rw partials
    __shared__ float  cst[8][8];         // per-h-pair constants for the p-pass
    __shared__ float  a_s;

    // ---- per-capsule data (thread t <-> capsule i = t) ----
    const int i  = t;
    const int Bc = i / 9, uv = i - Bc * 9, u = uv / 3, v = uv - u * 3;
    const float av = act[((b * BCAP + Bc) * WIN + (2 * xw + u)) * WIN + (2 * yw + v)];

    float Rv;                    // this thread's Rw (for i = t)
    __half2 vh[8];               // column slices: V[32w+sub+4k][2q..2q+1]
    uint4 row0, row1;            // this thread's own vote row V[i][0..15]
    const __half2* vpc = reinterpret_cast<const __half2*>(g_votes_h + colbase * 16);

    if (PHASE == 0) {
        const float4* Pp = reinterpret_cast<const float4*>(
            poses + ((size_t)((b * BCAP + Bc) * WIN + (2 * xw + u)) * WIN + (2 * yw + v)) * 16);
        const float4* Wp = reinterpret_cast<const float4*>(
            Wt + (size_t)(((Bc * 3 + u) * 3 + v) * NC + c) * 16);
        float4 p0 = Pp[0], p1 = Pp[1], p2 = Pp[2], p3 = Pp[3];
        float4 w0 = Wp[0], w1 = Wp[1], w2 = Wp[2], w3 = Wp[3];
        float4 r0 = rowmul(w0, p0, p1, p2, p3);
        float4 r1 = rowmul(w1, p0, p1, p2, p3);
        float4 r2 = rowmul(w2, p0, p1, p2, p3);
        float4 r3 = rowmul(w3, p0, p1, p2, p3);
        row0 = make_uint4(h2u(__floats2half2_rn(r0.x, r0.y)), h2u(__floats2half2_rn(r0.z, r0.w)),
                          h2u(__floats2half2_rn(r1.x, r1.y)), h2u(__floats2half2_rn(r1.z, r1.w)));
        row1 = make_uint4(h2u(__floats2half2_rn(r2.x, r2.y)), h2u(__floats2half2_rn(r2.z, r2.w)),
                          h2u(__floats2half2_rn(r3.x, r3.y)), h2u(__floats2half2_rn(r3.z, r3.w)));
        uint4* vg = reinterpret_cast<uint4*>(g_votes_h + colbase * 16 + (size_t)i * 16);
        vg[0] = row0; vg[1] = row1;
        Rv = (1.0f / 32.0f) * av;
        __syncthreads();   // votes visible block-wide (gmem round-trip)
        #pragma unroll
        for (int k = 0; k < 8; k++) vh[k] = vpc[(32 * w + sub + 4 * k) * 8 + q];
    } else {
        // vote loads first (max MLP); NO barrier needed — Rw exchange is intra-warp
        #pragma unroll
        for (int k = 0; k < 8; k++) vh[k] = vpc[(32 * w + sub + 4 * k) * 8 + q];
        Rv = (g_ap[colbase + i] * rcpf(g_denom[b * BKK + i] + EPSV) + EPSV) * av;
    }

    // ---- fused statistics pass: sum Rw*V, Rw*V^2, Rw over warp-local i ----
    float2 accm = make_float2(0.f, 0.f);
    float2 accv = make_float2(0.f, 0.f);
    float  accr = 0.f;
    #pragma unroll
    for (int k = 0; k < 8; k++) {
        const float rw = __shfl_sync(FULLM, Rv, sub + 4 * k);   // lane sub+4k holds i=32w+sub+4k
        const float2 vv = __half22float2(vh[k]);
        const float tx = rw * vv.x;
        const float ty = rw * vv.y;
        accm.x += tx;                 accm.y += ty;
        accv.x = fmaf(tx, vv.x, accv.x);
        accv.y = fmaf(ty, vv.y, accv.y);
        accr += rw;
    }
    // combine the 4 i-subgroups (lanes sharing q are consecutive: 4q..4q+3)
    accm.x += __shfl_xor_sync(FULLM, accm.x, 1);
    accm.y += __shfl_xor_sync(FULLM, accm.y, 1);
    accv.x += __shfl_xor_sync(FULLM, accv.x, 1);
    accv.y += __shfl_xor_sync(FULLM, accv.y, 1);
    accr   += __shfl_xor_sync(FULLM, accr,   1);
    accm.x += __shfl_xor_sync(FULLM, accm.x, 2);
    accm.y += __shfl_xor_sync(FULLM, accm.y, 2);
    accv.x += __shfl_xor_sync(FULLM, accv.x, 2);
    accv.y += __shfl_xor_sync(FULLM, accv.y, 2);
    accr   += __shfl_xor_sync(FULLM, accr,   2);
    if (sub == 0) {
        redm[w][q] = accm;
        redv[w][q] = accv;
        if (lane == 0) red2[w] = accr;
    }
    __syncthreads();

    // ---- issue the row re-load NOW (phase 1) so it overlaps the serial tail ----
    if (PHASE == 1) {
        const uint4* vg = reinterpret_cast<const uint4*>(g_votes_h + colbase * 16 + (size_t)i * 16);
        row0 = vg[0]; row1 = vg[1];   // L1/L2 hot: same 9KB the block just read as columns
    }

    // ---- serial tail: 16 threads compute per-h stats ----
    if (t < 16) {
        const float* rm = reinterpret_cast<const float*>(redm);
        const float* rv = reinterpret_cast<const float*>(redv);
        float rsum = 0.f, vsum = 0.f, sr = 0.f;
        #pragma unroll
        for (int j = 0; j < 9; j++) {
            rsum += rm[j * 16 + t];
            vsum += rv[j * 16 + t];
            sr   += red2[j];
        }
        const float rs = rcpf(sr);
        const float mu = rsum * rs;
        const float sig = fmaxf(vsum * rs - mu * mu, 1e-12f);
        const float ls = 0.5f * __logf(sig);          // log(sqrt(sig))
        if (PHASE == 2) {
            out[(size_t)(b * CWW + c * WW + s) * 16 + t] = mu;
        } else {
            const int hp = t >> 1, par = t & 1;
            cst[hp][par]     = mu;
            cst[hp][2 + par] = (0.5f * LOG2E) * rcpf(sig);
            cst[hp][4 + par] = -(ls + HALF_LN2PI) * LOG2E;
        }
        float lsum = ls;
        lsum += __shfl_xor_sync(0x0000ffffu, lsum, 1);
        lsum += __shfl_xor_sync(0x0000ffffu, lsum, 2);
        lsum += __shfl_xor_sync(0x0000ffffu, lsum, 4);
        lsum += __shfl_xor_sync(0x0000ffffu, lsum, 8);
        if (t == 0) {
            const float cost = sr * (16.f * beta_v[c] + lsum);
            const float z = lam[0] * (beta_a[c] - cost);
            const float aa = 1.f / (1.f + __expf(-z));
            if (PHASE == 2) out[(size_t)NB * CWW * 16 + b * CWW + c * WW + s] = aa;
            else            a_s = aa;
        }
    }
    if (PHASE == 2) return;
    __syncthreads();

    // ---- p-pass (row-major): thread t sums over all 16 h of its own row i=t ----
    const __half2 rowh[8] = {
        *reinterpret_cast<const __half2*>(&row0.x), *reinterpret_cast<const __half2*>(&row0.y),
        *reinterpret_cast<const __half2*>(&row0.z), *reinterpret_cast<const __half2*>(&row0.w),
        *reinterpret_cast<const __half2*>(&row1.x), *reinterpret_cast<const __half2*>(&row1.y),
        *reinterpret_cast<const __half2*>(&row1.z), *reinterpret_cast<const __half2*>(&row1.w)
    };
    float ap_acc = 0.f;
    #pragma unroll
    for (int hp = 0; hp < 8; hp++) {
        const float4 c0 = *reinterpret_cast<const float4*>(&cst[hp][0]);  // mu.x mu.y il.x il.y
        const float2 c1 = *reinterpret_cast<const float2*>(&cst[hp][4]);  // lc.x lc.y
        const float2 vv = __half22float2(rowh[hp]);
        const float dx = vv.x - c0.x;
        const float dy = vv.y - c0.y;
        ap_acc += ex2f(fmaf(-dx * dx, c0.z, c1.x)) + ex2f(fmaf(-dy * dy, c0.w, c1.y));
    }
    g_ap[colbase + t] = a_s * ap_acc;   // one fully-coalesced 1152B store per block
}

// Stage 1: block (j,b) sums 32 consecutive x-rows of ap -> g_part[b][j][i].
__global__ __launch_bounds__(BKK)
void denom_part_kernel()
{
    const int j = blockIdx.x;       // 0..35
    const int b = blockIdx.y;
    const int i = threadIdx.x;
    const float* ap = g_ap + (size_t)(b * CWW + j * 32) * BKK + i;
    float sv = 0.f;
    #pragma unroll 8
    for (int r = 0; r < 32; r++) sv += ap[(size_t)r * BKK];
    g_part[(b * 36 + j) * BKK + i] = sv;
}

// Stage 2: denom[b][i] = sum of the 36 partials.
__global__ __launch_bounds__(BKK)
void denom_final_kernel()
{
    const int b = blockIdx.x;
    const int i = threadIdx.x;
    const float* pp = g_part + b * 36 * BKK + i;
    float sv = 0.f;
    #pragma unroll
    for (int j = 0; j < 36; j++) sv += pp[j * BKK];
    g_denom[b * BKK + i] = sv;
}

extern "C" void kernel_launch(void* const* d_in, const int* in_sizes, int n_in,
                              void* d_out, int out_size)
{
    (void)in_sizes; (void)n_in; (void)out_size;
    const float* poses = (const float*)d_in[0];
    const float* act   = (const float*)d_in[1];
    const float* Wt    = (const float*)d_in[2];
    const float* bv    = (const float*)d_in[3];
    const float* ba    = (const float*)d_in[4];
    const float* lam   = (const float*)d_in[5];
    float* out = (float*)d_out;

    dim3 grid(CWW, NB);
    em_kernel<0><<<grid, BKK>>>(poses, act, Wt, bv, ba, lam, out);
    denom_part_kernel<<<dim3(36, NB), BKK>>>();
    denom_final_kernel<<<NB, BKK>>>();
    em_kernel<1><<<grid, BKK>>>(poses, act, Wt, bv, ba, lam, out);
    denom_part_kernel<<<dim3(36, NB), BKK>>>();
    denom_final_kernel<<<NB, BKK>>>();
    em_kernel<2><<<grid, BKK>>>(poses, act, Wt, bv, ba, lam, out);
}

// round 14
// speedup vs baseline: 1.0099x; 1.0099x over previous
#include <cuda_runtime.h>
#include <cuda_fp16.h>
#include <math.h>

// ---------------- problem constants ----------------
#define NB    8      // batch
#define BCAP  32     // B_ input capsules
#define NC    32     // C_ output capsules
#define WIN   14
#define WOUT  6
#define WW    36     // WOUT*WOUT
#define BKK   288    // K*K*B_
#define CWW   1152   // C_*WOUT*WOUT
#define EPSV  1e-10f
#define HALF_LN2PI 0.91893853320467274178f
#define LOG2E 1.4426950408889634074f
#define FULLM 0xffffffffu

// ---------------- device scratch (static: allocation-free) ----------------
__device__ __half g_votes_h[(size_t)NB * CWW * BKK * 16];  // 81 MB fp16 votes [b][x][i][h]
__device__ float  g_ap[(size_t)NB * CWW * BKK];            // R numerators [b][x][i]
__device__ float  g_part[NB * 36 * BKK];                   // stage-1 partial sums
__device__ float  g_denom[NB * BKK];                       // denom[b][i]

__device__ __forceinline__ float4 rowmul(float4 wr, float4 p0, float4 p1, float4 p2, float4 p3) {
    float4 r;
    r.x = wr.x*p0.x + wr.y*p1.x + wr.z*p2.x + wr.w*p3.x;
    r.y = wr.x*p0.y + wr.y*p1.y + wr.z*p2.y + wr.w*p3.y;
    r.z = wr.x*p0.z + wr.y*p1.z + wr.z*p2.z + wr.w*p3.z;
    r.w = wr.x*p0.w + wr.y*p1.w + wr.z*p2.w + wr.w*p3.w;
    return r;
}

__device__ __forceinline__ unsigned int h2u(__half2 x) {
    return *reinterpret_cast<unsigned int*>(&x);
}

__device__ __forceinline__ float ex2f(float x) {
    float y;
    asm("ex2.approx.ftz.f32 %0, %1;" : "=f"(y) : "f"(x));
    return y;
}

__device__ __forceinline__ float rcpf(float x) {
    float y;
    asm("rcp.approx.ftz.f32 %0, %1;" : "=f"(y) : "f"(x));
    return y;
}

// ---- L2 residency via createpolicy + cache_hint (votes ~81MB vs ~126MB L2) ----
__device__ __forceinline__ unsigned long long mk_evict_last_policy() {
    unsigned long long pol;
    asm("createpolicy.fractional.L2::evict_last.b64 %0, 1.0;" : "=l"(pol));
    return pol;
}
__device__ __forceinline__ unsigned int ldg_el_b32(const void* p, unsigned long long pol) {
    unsigned int r;
    asm("ld.global.L2::cache_hint.b32 %0, [%1], %2;" : "=r"(r) : "l"(p), "l"(pol));
    return r;
}
__device__ __forceinline__ uint4 ldg_el_v4(const void* p, unsigned long long pol) {
    uint4 r;
    asm("ld.global.L2::cache_hint.v4.b32 {%0,%1,%2,%3}, [%4], %5;"
        : "=r"(r.x), "=r"(r.y), "=r"(r.z), "=r"(r.w) : "l"(p), "l"(pol));
    return r;
}
__device__ __forceinline__ void stg_el_v4(void* p, uint4 v, unsigned long long pol) {
    asm volatile("st.global.L2::cache_hint.v4.b32 [%0], {%1,%2,%3,%4}, %5;"
                 :: "l"(p), "r"(v.x), "r"(v.y), "r"(v.z), "r"(v.w), "l"(pol) : "memory");
}

// One block per output column. blockIdx.x = x = s*32 + c. 288 threads, 9 warps.
// Stats mapping is WARP-LOCAL: warp w owns capsules i in [32w, 32w+32).
// Thread (lane) takes sub = lane&3, q = lane>>2 and reduces i = 32w+sub+4k,
// k=0..7, h-pair q. Rw exchanged via __shfl -> no pre-stats barrier in 1/2.
// Votes are stored/loaded with an L2 evict_last cache-hint policy so the 81MB
// tensor stays L2-resident across phases (phase 2, the last reader, default).
// p-pass: thread t re-reads its OWN row V[i=t][0..15]; g_ap store coalesced.
template <int PHASE>
__global__ __launch_bounds__(BKK, 5)
void em_kernel(const float* __restrict__ poses, const float* __restrict__ act,
               const float* __restrict__ Wt, const float* __restrict__ beta_v,
               const float* __restrict__ beta_a, const float* __restrict__ lam,
               float* __restrict__ out)
{
    const int x   = blockIdx.x;
    const int b   = blockIdx.y;
    const int c   = x & 31;
    const int s   = x >> 5;
    const int yw  = s / WOUT;
    const int xw  = s - yw * WOUT;
    const int t   = threadIdx.x;
    const int w   = t >> 5;        // warp 0..8
    const int lane = t & 31;
    const int sub = lane & 3;      // i-subgroup within warp
    const int q   = lane >> 2;     // 0..7 (h-pair)
    const size_t colbase = (size_t)(b * CWW + x) * BKK;

    __shared__ float2 redm[9][8];        // Rw*V partials (float[9][16] view)
    __shared__ float2 redv[9][8];        // Rw*V^2 partials
    __shared__ float  red2[9];           // Rw partials
    __shared__ float  cst[8][8];         // per-h-pair constants for the p-pass
    __shared__ float  a_s;

    // ---- per-capsule data (thread t <-> capsule i = t) ----
    const int i  = t;
    const int Bc = i / 9, uv = i - Bc * 9, u = uv / 3, v = uv - u * 3;
    const float av = act[((b * BCAP + Bc) * WIN + (2 * xw + u)) * WIN + (2 * yw + v)];

    float Rv;                    // this thread's Rw (for i = t)
    __half2 vh[8];               // column slices: V[32w+sub+4k][2q..2q+1]
    uint4 row0, row1;            // this thread's own vote row V[i][0..15]
    const __half2* vpc = reinterpret_cast<const __half2*>(g_votes_h + colbase * 16);
    const unsigned long long pol = mk_evict_last_policy();

    if (PHASE == 0) {
        const float4* Pp = reinterpret_cast<const float4*>(
            poses + ((size_t)((b * BCAP + Bc) * WIN + (2 * xw + u)) * WIN + (2 * yw + v)) * 16);
        const float4* Wp = reinterpret_cast<const float4*>(
            Wt + (size_t)(((Bc * 3 + u) * 3 + v) * NC + c) * 16);
        float4 p0 = Pp[0], p1 = Pp[1], p2 = Pp[2], p3 = Pp[3];
        float4 w0 = Wp[0], w1 = Wp[1], w2 = Wp[2], w3 = Wp[3];
        float4 r0 = rowmul(w0, p0, p1, p2, p3);
        float4 r1 = rowmul(w1, p0, p1, p2, p3);
        float4 r2 = rowmul(w2, p0, p1, p2, p3);
        float4 r3 = rowmul(w3, p0, p1, p2, p3);
        row0 = make_uint4(h2u(__floats2half2_rn(r0.x, r0.y)), h2u(__floats2half2_rn(r0.z, r0.w)),
                          h2u(__floats2half2_rn(r1.x, r1.y)), h2u(__floats2half2_rn(r1.z, r1.w)));
        row1 = make_uint4(h2u(__floats2half2_rn(r2.x, r2.y)), h2u(__floats2half2_rn(r2.z, r2.w)),
                          h2u(__floats2half2_rn(r3.x, r3.y)), h2u(__floats2half2_rn(r3.z, r3.w)));
        __half* vgp = g_votes_h + colbase * 16 + (size_t)i * 16;
        stg_el_v4(vgp, row0, pol);
        stg_el_v4(vgp + 8, row1, pol);
        Rv = (1.0f / 32.0f) * av;
        __syncthreads();   // votes visible block-wide (gmem round-trip)
        #pragma unroll
        for (int k = 0; k < 8; k++) {
            unsigned int r = ldg_el_b32(vpc + (32 * w + sub + 4 * k) * 8 + q, pol);
            vh[k] = *reinterpret_cast<__half2*>(&r);
        }
    } else if (PHASE == 1) {
        // vote loads first (max MLP); no barrier — Rw exchange is intra-warp
        #pragma unroll
        for (int k = 0; k < 8; k++) {
            unsigned int r = ldg_el_b32(vpc + (32 * w + sub + 4 * k) * 8 + q, pol);
            vh[k] = *reinterpret_cast<__half2*>(&r);
        }
        Rv = (g_ap[colbase + i] * rcpf(g_denom[b * BKK + i] + EPSV) + EPSV) * av;
    } else {
        // PHASE 2: last reader — default eviction priority (let votes age out)
        #pragma unroll
        for (int k = 0; k < 8; k++) vh[k] = vpc[(32 * w + sub + 4 * k) * 8 + q];
        Rv = (g_ap[colbase + i] * rcpf(g_denom[b * BKK + i] + EPSV) + EPSV) * av;
    }

    // ---- fused statistics pass: sum Rw*V, Rw*V^2, Rw over warp-local i ----
    float2 accm = make_float2(0.f, 0.f);
    float2 accv = make_float2(0.f, 0.f);
    float  accr = 0.f;
    #pragma unroll
    for (int k = 0; k < 8; k++) {
        const float rw = __shfl_sync(FULLM, Rv, sub + 4 * k);   // lane sub+4k holds i=32w+sub+4k
        const float2 vv = __half22float2(vh[k]);
        const float tx = rw * vv.x;
        const float ty = rw * vv.y;
        accm.x += tx;                 accm.y += ty;
        accv.x = fmaf(tx, vv.x, accv.x);
        accv.y = fmaf(ty, vv.y, accv.y);
        accr += rw;
    }
    // combine the 4 i-subgroups (lanes sharing q are consecutive: 4q..4q+3)
    accm.x += __shfl_xor_sync(FULLM, accm.x, 1);
    accm.y += __shfl_xor_sync(FULLM, accm.y, 1);
    accv.x += __shfl_xor_sync(FULLM, accv.x, 1);
    accv.y += __shfl_xor_sync(FULLM, accv.y, 1);
    accr   += __shfl_xor_sync(FULLM, accr,   1);
    accm.x += __shfl_xor_sync(FULLM, accm.x, 2);
    accm.y += __shfl_xor_sync(FULLM, accm.y, 2);
    accv.x += __shfl_xor_sync(FULLM, accv.x, 2);
    accv.y += __shfl_xor_sync(FULLM, accv.y, 2);
    accr   += __shfl_xor_sync(FULLM, accr,   2);
    if (sub == 0) {
        redm[w][q] = accm;
        redv[w][q] = accv;
        if (lane == 0) red2[w] = accr;
    }
    __syncthreads();

    // ---- issue the row re-load NOW (phase 1) so it overlaps the serial tail ----
    if (PHASE == 1) {
        const __half* vgp = g_votes_h + colbase * 16 + (size_t)i * 16;
        row0 = ldg_el_v4(vgp, pol);   // L1/L2 hot: same 9KB the block just read as columns
        row1 = ldg_el_v4(vgp + 8, pol);
    }

    // ---- serial tail: 16 threads compute per-h stats ----
    if (t < 16) {
        const float* rm = reinterpret_cast<const float*>(redm);
        const float* rv = reinterpret_cast<const float*>(redv);
        float rsum = 0.f, vsum = 0.f, sr = 0.f;
        #pragma unroll
        for (int j = 0; j < 9; j++) {
            rsum += rm[j * 16 + t];
            vsum += rv[j * 16 + t];
            sr   += red2[j];
        }
        const float rs = rcpf(sr);
        const float mu = rsum * rs;
        const float sig = fmaxf(vsum * rs - mu * mu, 1e-12f);
        const float ls = 0.5f * __logf(sig);          // log(sqrt(sig))
        if (PHASE == 2) {
            out[(size_t)(b * CWW + c * WW + s) * 16 + t] = mu;
        } else {
            const int hp = t >> 1, par = t & 1;
            cst[hp][par]     = mu;
            cst[hp][2 + par] = (0.5f * LOG2E) * rcpf(sig);
            cst[hp][4 + par] = -(ls + HALF_LN2PI) * LOG2E;
        }
        float lsum = ls;
        lsum += __shfl_xor_sync(0x0000ffffu, lsum, 1);
        lsum += __shfl_xor_sync(0x0000ffffu, lsum, 2);
        lsum += __shfl_xor_sync(0x0000ffffu, lsum, 4);
        lsum += __shfl_xor_sync(0x0000ffffu, lsum, 8);
        if (t == 0) {
            const float cost = sr * (16.f * beta_v[c] + lsum);
            const float z = lam[0] * (beta_a[c] - cost);
            const float aa = 1.f / (1.f + __expf(-z));
            if (PHASE == 2) out[(size_t)NB * CWW * 16 + b * CWW + c * WW + s] = aa;
            else            a_s = aa;
        }
    }
    if (PHASE == 2) return;
    __syncthreads();

    // ---- p-pass (row-major): thread t sums over all 16 h of its own row i=t ----
    const __half2 rowh[8] = {
        *reinterpret_cast<const __half2*>(&row0.x), *reinterpret_cast<const __half2*>(&row0.y),
        *reinterpret_cast<const __half2*>(&row0.z), *reinterpret_cast<const __half2*>(&row0.w),
        *reinterpret_cast<const __half2*>(&row1.x), *reinterpret_cast<const __half2*>(&row1.y),
        *reinterpret_cast<const __half2*>(&row1.z), *reinterpret_cast<const __half2*>(&row1.w)
    };
    float ap_acc = 0.f;
    #pragma unroll
    for (int hp = 0; hp < 8; hp++) {
        const float4 c0 = *reinterpret_cast<const float4*>(&cst[hp][0]);  // mu.x mu.y il.x il.y
        const float2 c1 = *reinterpret_cast<const float2*>(&cst[hp][4]);  // lc.x lc.y
        const float2 vv = __half22float2(rowh[hp]);
        const float dx = vv.x - c0.x;
        const float dy = vv.y - c0.y;
        ap_acc += ex2f(fmaf(-dx * dx, c0.z, c1.x)) + ex2f(fmaf(-dy * dy, c0.w, c1.y));
    }
    g_ap[colbase + t] = a_s * ap_acc;   // one fully-coalesced 1152B store per block
}

// Stage 1: block (j,b) sums 32 consecutive x-rows of ap -> g_part[b][j][i].
__global__ __launch_bounds__(BKK)
void denom_part_kernel()
{
    const int j = blockIdx.x;       // 0..35
    const int b = blockIdx.y;
    const int i = threadIdx.x;
    const float* ap = g_ap + (size_t)(b * CWW + j * 32) * BKK + i;
    float sv = 0.f;
    #pragma unroll 8
    for (int r = 0; r < 32; r++) sv += ap[(size_t)r * BKK];
    g_part[(b * 36 + j) * BKK + i] = sv;
}

// Stage 2: denom[b][i] = sum of the 36 partials.
__global__ __launch_bounds__(BKK)
void denom_final_kernel()
{
    const int b = blockIdx.x;
    const int i = threadIdx.x;
    const float* pp = g_part + b * 36 * BKK + i;
    float sv = 0.f;
    #pragma unroll
    for (int j = 0; j < 36; j++) sv += pp[j * BKK];
    g_denom[b * BKK + i] = sv;
}

extern "C" void kernel_launch(void* const* d_in, const int* in_sizes, int n_in,
                              void* d_out, int out_size)
{
    (void)in_sizes; (void)n_in; (void)out_size;
    const float* poses = (const float*)d_in[0];
    const float* act   = (const float*)d_in[1];
    const float* Wt    = (const float*)d_in[2];
    const float* bv    = (const float*)d_in[3];
    const float* ba    = (const float*)d_in[4];
    const float* lam   = (const float*)d_in[5];
    float* out = (float*)d_out;

    dim3 grid(CWW, NB);
    em_kernel<0><<<grid, BKK>>>(poses, act, Wt, bv, ba, lam, out);
    denom_part_kernel<<<dim3(36, NB), BKK>>>();
    denom_final_kernel<<<NB, BKK>>>();
    em_kernel<1><<<grid, BKK>>>(poses, act, Wt, bv, ba, lam, out);
    denom_part_kernel<<<dim3(36, NB), BKK>>>();
    denom_final_kernel<<<NB, BKK>>>();
    em_kernel<2><<<grid, BKK>>>(poses, act, Wt, bv, ba, lam, out);
}

// round 15
// speedup vs baseline: 1.0212x; 1.0112x over previous
#include <cuda_runtime.h>
#include <cuda_fp16.h>
#include <math.h>

// ---------------- problem constants ----------------
#define NB    8      // batch
#define BCAP  32     // B_ input capsules
#define NC    32     // C_ output capsules
#define WIN   14
#define WOUT  6
#define WW    36     // WOUT*WOUT
#define BKK   288    // K*K*B_
#define CWW   1152   // C_*WOUT*WOUT
#define EPSV  1e-10f
#define HALF_LN2PI 0.91893853320467274178f
#define LOG2E 1.4426950408889634074f
#define FULLM 0xffffffffu

// ---------------- device scratch (static: allocation-free) ----------------
__device__ __half g_votes_h[(size_t)NB * CWW * BKK * 16];  // 81 MB fp16 votes [b][x][i][h]
__device__ float  g_ap[(size_t)NB * CWW * BKK];            // R numerators [b][x][i]
__device__ float  g_part[NB * 36 * BKK];                   // stage-1 partial sums
__device__ float  g_denom[NB * BKK];                       // denom[b][i]

__device__ __forceinline__ float4 rowmul(float4 wr, float4 p0, float4 p1, float4 p2, float4 p3) {
    float4 r;
    r.x = wr.x*p0.x + wr.y*p1.x + wr.z*p2.x + wr.w*p3.x;
    r.y = wr.x*p0.y + wr.y*p1.y + wr.z*p2.y + wr.w*p3.y;
    r.z = wr.x*p0.z + wr.y*p1.z + wr.z*p2.z + wr.w*p3.z;
    r.w = wr.x*p0.w + wr.y*p1.w + wr.z*p2.w + wr.w*p3.w;
    return r;
}

__device__ __forceinline__ unsigned int h2u(__half2 x) {
    return *reinterpret_cast<unsigned int*>(&x);
}

__device__ __forceinline__ float ex2f(float x) {
    float y;
    asm("ex2.approx.ftz.f32 %0, %1;" : "=f"(y) : "f"(x));
    return y;
}

__device__ __forceinline__ float rcpf(float x) {
    float y;
    asm("rcp.approx.ftz.f32 %0, %1;" : "=f"(y) : "f"(x));
    return y;
}

// ---- L2 cache-hint policy (kept from R14: small but real store-side win) ----
__device__ __forceinline__ unsigned long long mk_evict_last_policy() {
    unsigned long long pol;
    asm("createpolicy.fractional.L2::evict_last.b64 %0, 1.0;" : "=l"(pol));
    return pol;
}
__device__ __forceinline__ unsigned int ldg_el_b32(const void* p, unsigned long long pol) {
    unsigned int r;
    asm("ld.global.L2::cache_hint.b32 %0, [%1], %2;" : "=r"(r) : "l"(p), "l"(pol));
    return r;
}
__device__ __forceinline__ uint4 ldg_el_v4(const void* p, unsigned long long pol) {
    uint4 r;
    asm("ld.global.L2::cache_hint.v4.b32 {%0,%1,%2,%3}, [%4], %5;"
        : "=r"(r.x), "=r"(r.y), "=r"(r.z), "=r"(r.w) : "l"(p), "l"(pol));
    return r;
}
__device__ __forceinline__ void stg_el_v4(void* p, uint4 v, unsigned long long pol) {
    asm volatile("st.global.L2::cache_hint.v4.b32 [%0], {%1,%2,%3,%4}, %5;"
                 :: "l"(p), "r"(v.x), "r"(v.y), "r"(v.z), "r"(v.w), "l"(pol) : "memory");
}

// One block per output column. blockIdx.x = x = s*32 + c. 288 threads, 9 warps.
// Stats mapping WARP-LOCAL: warp w owns capsules [32w,32w+32); lane sub=lane&3,
// q=lane>>2 reduces i=32w+sub+4k, h-pair q (fp32 accumulation, unchanged).
// p-pass now in PACKED fp16: per h-pair one hsub2/hmul2/hfma2/h2exp2 chain with
// constants (mu, -il, lc in exp2 units) packed as half2 rows in cst_h[8][8]
// (one LDS.128 per hp). il clamped <=6e4 so 0*inf NaN cannot form; dd*(-il)
// overflow -> -inf -> exp2 -> 0 matches fp32 underflow semantics.
template <int PHASE>
__global__ __launch_bounds__(BKK, 5)
void em_kernel(const float* __restrict__ poses, const float* __restrict__ act,
               const float* __restrict__ Wt, const float* __restrict__ beta_v,
               const float* __restrict__ beta_a, const float* __restrict__ lam,
               float* __restrict__ out)
{
    const int x   = blockIdx.x;
    const int b   = blockIdx.y;
    const int c   = x & 31;
    const int s   = x >> 5;
    const int yw  = s / WOUT;
    const int xw  = s - yw * WOUT;
    const int t   = threadIdx.x;
    const int w   = t >> 5;        // warp 0..8
    const int lane = t & 31;
    const int sub = lane & 3;      // i-subgroup within warp
    const int q   = lane >> 2;     // 0..7 (h-pair)
    const size_t colbase = (size_t)(b * CWW + x) * BKK;

    __shared__ float2 redm[9][8];        // Rw*V partials (float[9][16] view)
    __shared__ float2 redv[9][8];        // Rw*V^2 partials
    __shared__ float  red2[9];           // Rw partials
    __shared__ __align__(16) __half cst_h[8][8];  // [hp]: {mu2, nil2, lc2, pad} as halves
    __shared__ float  a_s;

    // ---- per-capsule data (thread t <-> capsule i = t) ----
    const int i  = t;
    const int Bc = i / 9, uv = i - Bc * 9, u = uv / 3, v = uv - u * 3;
    const float av = act[((b * BCAP + Bc) * WIN + (2 * xw + u)) * WIN + (2 * yw + v)];

    float Rv;                    // this thread's Rw (for i = t)
    __half2 vh[8];               // column slices: V[32w+sub+4k][2q..2q+1]
    uint4 row0, row1;            // this thread's own vote row V[i][0..15]
    const __half2* vpc = reinterpret_cast<const __half2*>(g_votes_h + colbase * 16);
    const unsigned long long pol = mk_evict_last_policy();

    if (PHASE == 0) {
        const float4* Pp = reinterpret_cast<const float4*>(
            poses + ((size_t)((b * BCAP + Bc) * WIN + (2 * xw + u)) * WIN + (2 * yw + v)) * 16);
        const float4* Wp = reinterpret_cast<const float4*>(
            Wt + (size_t)(((Bc * 3 + u) * 3 + v) * NC + c) * 16);
        float4 p0 = Pp[0], p1 = Pp[1], p2 = Pp[2], p3 = Pp[3];
        float4 w0 = Wp[0], w1 = Wp[1], w2 = Wp[2], w3 = Wp[3];
        float4 r0 = rowmul(w0, p0, p1, p2, p3);
        float4 r1 = rowmul(w1, p0, p1, p2, p3);
        float4 r2 = rowmul(w2, p0, p1, p2, p3);
        float4 r3 = rowmul(w3, p0, p1, p2, p3);
        row0 = make_uint4(h2u(__floats2half2_rn(r0.x, r0.y)), h2u(__floats2half2_rn(r0.z, r0.w)),
                          h2u(__floats2half2_rn(r1.x, r1.y)), h2u(__floats2half2_rn(r1.z, r1.w)));
        row1 = make_uint4(h2u(__floats2half2_rn(r2.x, r2.y)), h2u(__floats2half2_rn(r2.z, r2.w)),
                          h2u(__floats2half2_rn(r3.x, r3.y)), h2u(__floats2half2_rn(r3.z, r3.w)));
        __half* vgp = g_votes_h + colbase * 16 + (size_t)i * 16;
        stg_el_v4(vgp, row0, pol);
        stg_el_v4(vgp + 8, row1, pol);
        Rv = (1.0f / 32.0f) * av;
        __syncthreads();   // votes visible block-wide (gmem round-trip)
        #pragma unroll
        for (int k = 0; k < 8; k++) {
            unsigned int r = ldg_el_b32(vpc + (32 * w + sub + 4 * k) * 8 + q, pol);
            vh[k] = *reinterpret_cast<__half2*>(&r);
        }
    } else if (PHASE == 1) {
        // vote loads first (max MLP); no barrier — Rw exchange is intra-warp
        #pragma unroll
        for (int k = 0; k < 8; k++) {
            unsigned int r = ldg_el_b32(vpc + (32 * w + sub + 4 * k) * 8 + q, pol);
            vh[k] = *reinterpret_cast<__half2*>(&r);
        }
        Rv = (g_ap[colbase + i] * rcpf(g_denom[b * BKK + i] + EPSV) + EPSV) * av;
    } else {
        // PHASE 2: last reader — default eviction priority (let votes age out)
        #pragma unroll
        for (int k = 0; k < 8; k++) vh[k] = vpc[(32 * w + sub + 4 * k) * 8 + q];
        Rv = (g_ap[colbase + i] * rcpf(g_denom[b * BKK + i] + EPSV) + EPSV) * av;
    }

    // ---- fused statistics pass: sum Rw*V, Rw*V^2, Rw over warp-local i (fp32) ----
    float2 accm = make_float2(0.f, 0.f);
    float2 accv = make_float2(0.f, 0.f);
    float  accr = 0.f;
    #pragma unroll
    for (int k = 0; k < 8; k++) {
        const float rw = __shfl_sync(FULLM, Rv, sub + 4 * k);   // lane sub+4k holds i=32w+sub+4k
        const float2 vv = __half22float2(vh[k]);
        const float tx = rw * vv.x;
        const float ty = rw * vv.y;
        accm.x += tx;                 accm.y += ty;
        accv.x = fmaf(tx, vv.x, accv.x);
        accv.y = fmaf(ty, vv.y, accv.y);
        accr += rw;
    }
    // combine the 4 i-subgroups (lanes sharing q are consecutive: 4q..4q+3)
    accm.x += __shfl_xor_sync(FULLM, accm.x, 1);
    accm.y += __shfl_xor_sync(FULLM, accm.y, 1);
    accv.x += __shfl_xor_sync(FULLM, accv.x, 1);
    accv.y += __shfl_xor_sync(FULLM, accv.y, 1);
    accr   += __shfl_xor_sync(FULLM, accr,   1);
    accm.x += __shfl_xor_sync(FULLM, accm.x, 2);
    accm.y += __shfl_xor_sync(FULLM, accm.y, 2);
    accv.x += __shfl_xor_sync(FULLM, accv.x, 2);
    accv.y += __shfl_xor_sync(FULLM, accv.y, 2);
    accr   += __shfl_xor_sync(FULLM, accr,   2);
    if (sub == 0) {
        redm[w][q] = accm;
        redv[w][q] = accv;
        if (lane == 0) red2[w] = accr;
    }
    __syncthreads();

    // ---- issue the row re-load NOW (phase 1) so it overlaps the serial tail ----
    if (PHASE == 1) {
        const __half* vgp = g_votes_h + colbase * 16 + (size_t)i * 16;
        row0 = ldg_el_v4(vgp, pol);   // L1/L2 hot: same 9KB the block just read as columns
        row1 = ldg_el_v4(vgp + 8, pol);
    }

    // ---- serial tail: 16 threads compute per-h stats ----
    if (t < 16) {
        const float* rm = reinterpret_cast<const float*>(redm);
        const float* rv = reinterpret_cast<const float*>(redv);
        float rsum = 0.f, vsum = 0.f, sr = 0.f;
        #pragma unroll
        for (int j = 0; j < 9; j++) {
            rsum += rm[j * 16 + t];
            vsum += rv[j * 16 + t];
            sr   += red2[j];
        }
        const float rs = rcpf(sr);
        const float mu = rsum * rs;
        const float sig = fmaxf(vsum * rs - mu * mu, 1e-12f);
        const float ls = 0.5f * __logf(sig);          // log(sqrt(sig))
        if (PHASE == 2) {
            out[(size_t)(b * CWW + c * WW + s) * 16 + t] = mu;
        } else {
            // pack p-pass constants as halves: [hp] = {mu2, -il2, lc2, pad}
            const int hp = t >> 1, par = t & 1;
            const float il = fminf((0.5f * LOG2E) * rcpf(sig), 6.0e4f);
            cst_h[hp][par]     = __float2half_rn(mu);
            cst_h[hp][2 + par] = __float2half_rn(-il);
            cst_h[hp][4 + par] = __float2half_rn(-(ls + HALF_LN2PI) * LOG2E);
        }
        float lsum = ls;
        lsum += __shfl_xor_sync(0x0000ffffu, lsum, 1);
        lsum += __shfl_xor_sync(0x0000ffffu, lsum, 2);
        lsum += __shfl_xor_sync(0x0000ffffu, lsum, 4);
        lsum += __shfl_xor_sync(0x0000ffffu, lsum, 8);
        if (t == 0) {
            const float cost = sr * (16.f * beta_v[c] + lsum);
            const float z = lam[0] * (beta_a[c] - cost);
            const float aa = 1.f / (1.f + __expf(-z));
            if (PHASE == 2) out[(size_t)NB * CWW * 16 + b * CWW + c * WW + s] = aa;
            else            a_s = aa;
        }
    }
    if (PHASE == 2) return;
    __syncthreads();

    // ---- p-pass (packed fp16): thread t sums 16 h of its own row i=t ----
    const __half2 rowh[8] = {
        *reinterpret_cast<const __half2*>(&row0.x), *reinterpret_cast<const __half2*>(&row0.y),
        *reinterpret_cast<const __half2*>(&row0.z), *reinterpret_cast<const __half2*>(&row0.w),
        *reinterpret_cast<const __half2*>(&row1.x), *reinterpret_cast<const __half2*>(&row1.y),
        *reinterpret_cast<const __half2*>(&row1.z), *reinterpret_cast<const __half2*>(&row1.w)
    };
    __half2 acc = __float2half2_rn(0.f);
    #pragma unroll
    for (int hp = 0; hp < 8; hp++) {
        const uint4 cc = *reinterpret_cast<const uint4*>(&cst_h[hp][0]);  // 1x LDS.128
        const __half2 mu2  = *reinterpret_cast<const __half2*>(&cc.x);
        const __half2 nil2 = *reinterpret_cast<const __half2*>(&cc.y);
        const __half2 lc2  = *reinterpret_cast<const __half2*>(&cc.z);
        const __half2 d  = __hsub2(rowh[hp], mu2);
        const __half2 e  = h2exp2(__hfma2(__hmul2(d, d), nil2, lc2));
        acc = __hadd2(acc, e);
    }
    const float2 af = __half22float2(acc);
    g_ap[colbase + t] = a_s * (af.x + af.y);   // one fully-coalesced 1152B store per block
}

// Stage 1: block (j,b) sums 32 consecutive x-rows of ap -> g_part[b][j][i].
__global__ __launch_bounds__(BKK)
void denom_part_kernel()
{
    const int j = blockIdx.x;       // 0..35
    const int b = blockIdx.y;
    const int i = threadIdx.x;
    const float* ap = g_ap + (size_t)(b * CWW + j * 32) * BKK + i;
    float sv = 0.f;
    #pragma unroll 8
    for (int r = 0; r < 32; r++) sv += ap[(size_t)r * BKK];
    g_part[(b * 36 + j) * BKK + i] = sv;
}

// Stage 2: denom[b][i] = sum of the 36 partials.
__global__ __launch_bounds__(BKK)
void denom_final_kernel()
{
    const int b = blockIdx.x;
    const int i = threadIdx.x;
    const float* pp = g_part + b * 36 * BKK + i;
    float sv = 0.f;
    #pragma unroll
    for (int j = 0; j < 36; j++) sv += pp[j * BKK];
    g_denom[b * BKK + i] = sv;
}

extern "C" void kernel_launch(void* const* d_in, const int* in_sizes, int n_in,
                              void* d_out, int out_size)
{
    (void)in_sizes; (void)n_in; (void)out_size;
    const float* poses = (const float*)d_in[0];
    const float* act   = (const float*)d_in[1];
    const float* Wt    = (const float*)d_in[2];
    const float* bv    = (const float*)d_in[3];
    const float* ba    = (const float*)d_in[4];
    const float* lam   = (const float*)d_in[5];
    float* out = (float*)d_out;

    dim3 grid(CWW, NB);
    em_kernel<0><<<grid, BKK>>>(poses, act, Wt, bv, ba, lam, out);
    denom_part_kernel<<<dim3(36, NB), BKK>>>();
    denom_final_kernel<<<NB, BKK>>>();
    em_kernel<1><<<grid, BKK>>>(poses, act, Wt, bv, ba, lam, out);
    denom_part_kernel<<<dim3(36, NB), BKK>>>();
    denom_final_kernel<<<NB, BKK>>>();
    em_kernel<2><<<grid, BKK>>>(poses, act, Wt, bv, ba, lam, out);
}